// round 1
// baseline (speedup 1.0000x reference)
#include <cuda_runtime.h>
#include <cstdint>

#define NPTS 50000
#define DIM  128
#define TANCH 1024
#define KNEG 10
#define GAMMA 1.0f

#define MA 16          // anchors per CTA
#define TN 256         // candidate tile
#define DC 16          // d-chunk
#define NCHUNK (DIM / DC)
#define SSEG 4
#define TILES_PER_SEG 49
#define SEG_LEN (TILES_PER_SEG * TN)   // 12544
#define N_PAD (SSEG * SEG_LEN)         // 50176

// ---------------- scratch (static device memory; no allocs) ----------------
__device__ float g_BT[2][DIM][N_PAD];            // [0]=out1^T, [1]=out2^T (padded with 1e30)
__device__ float g_segkd[2][TANCH][SSEG][KNEG];
__device__ int   g_segki[2][TANCH][SSEG][KNEG];
__device__ float g_partial[TANCH];

// ---------------- helpers ----------------
__device__ __forceinline__ void cp_async16(uint32_t s, const void* g) {
    asm volatile("cp.async.cg.shared.global [%0], [%1], 16;\n" :: "r"(s), "l"(g));
}
__device__ __forceinline__ void cp_commit() { asm volatile("cp.async.commit_group;\n"); }
template <int N> __device__ __forceinline__ void cp_wait() {
    asm volatile("cp.async.wait_group %0;\n" :: "n"(N));
}
__device__ __forceinline__ float warp_sum(float v) {
    #pragma unroll
    for (int o = 16; o > 0; o >>= 1) v += __shfl_xor_sync(0xffffffffu, v, o);
    return v;
}

// ---------------- kernel 1: transpose + pad ----------------
__global__ void transpose_pad_kernel(const float* __restrict__ out1,
                                     const float* __restrict__ out2) {
    __shared__ float tile[32][33];
    const float* src = (blockIdx.z == 0) ? out1 : out2;
    float* dst = &g_BT[blockIdx.z][0][0];
    int nBase = blockIdx.x * 32;
    int dBase = blockIdx.y * 32;
    #pragma unroll
    for (int j = 0; j < 32; j += 8) {
        int n = nBase + threadIdx.y + j;
        float v = 1.0e30f;
        if (n < NPTS) v = src[n * DIM + dBase + threadIdx.x];
        tile[threadIdx.y + j][threadIdx.x] = v;
    }
    __syncthreads();
    #pragma unroll
    for (int j = 0; j < 32; j += 8) {
        int d = dBase + threadIdx.y + j;
        dst[d * N_PAD + nBase + threadIdx.x] = tile[threadIdx.x][threadIdx.y + j];
    }
}

// ---------------- kernel 2: mining ----------------
__device__ __forceinline__ void load_chunk(float* sbuf, const float* __restrict__ BT,
                                           int n0, int chunk, int t) {
    uint32_t sbase = (uint32_t)__cvta_generic_to_shared(sbuf);
    #pragma unroll
    for (int i = 0; i < 4; ++i) {
        int f4 = t + i * 256;          // float4 index within [DC][TN]
        int d  = f4 >> 6;              // /(TN/4)
        int c4 = (f4 & 63) << 2;
        const float* g = BT + (chunk * DC + d) * N_PAD + n0 + c4;
        cp_async16(sbase + (uint32_t)((d * TN + c4) * 4), g);
    }
}

__global__ __launch_bounds__(256, 4)
void mine_kernel(const float* __restrict__ out1, const float* __restrict__ out2,
                 const int* __restrict__ anchor1, const int* __restrict__ anchor2) {
    __shared__ float As[DIM * MA];        // [d][a]   8 KB
    __shared__ float Bs[2][DC * TN];      // 2x16 KB  (Bs[0] reused as dist buffer)
    __shared__ float s_kd[MA][KNEG];
    __shared__ int   s_ki[MA][KNEG];

    const int dir = blockIdx.z;
    const int tBase = blockIdx.x * MA;
    const int seg = blockIdx.y;
    const float* Arows = (dir == 0) ? out1 : out2;
    const int*   anch  = (dir == 0) ? anchor1 : anchor2;
    const float* BT    = &g_BT[(dir == 0) ? 1 : 0][0][0];

    const int t = threadIdx.x;

    // Load 16 anchor rows (gathered) into As transposed: As[d*MA + a]
    {
        int a  = t >> 4;
        int d0 = (t & 15) * 8;
        const float* row = Arows + anch[tBase + a] * DIM;
        #pragma unroll
        for (int j = 0; j < 8; ++j) As[(d0 + j) * MA + a] = row[d0 + j];
    }
    if ((t & 15) == 0) {
        int a = t >> 4;
        #pragma unroll
        for (int k = 0; k < KNEG; ++k) { s_kd[a][k] = 3.0e38f; s_ki[a][k] = 0; }
    }
    __syncthreads();

    const int aBase = (t >> 6) * 4;   // warp-uniform: 0,4,8,12
    const int cBase = (t & 63) * 4;   // 0..252
    const int segStart = seg * SEG_LEN;

    for (int tile = 0; tile < TILES_PER_SEG; ++tile) {
        const int n0 = segStart + tile * TN;
        float acc[4][4];
        #pragma unroll
        for (int i = 0; i < 4; ++i)
            #pragma unroll
            for (int j = 0; j < 4; ++j) acc[i][j] = 0.0f;

        load_chunk(Bs[0], BT, n0, 0, t);
        cp_commit();

        for (int c = 0; c < NCHUNK; ++c) {
            if (c + 1 < NCHUNK) {
                load_chunk(Bs[(c + 1) & 1], BT, n0, c + 1, t);
                cp_commit();
                cp_wait<1>();
            } else {
                cp_wait<0>();
            }
            __syncthreads();
            const float* B = Bs[c & 1];
            const int d0 = c * DC;
            #pragma unroll
            for (int d = 0; d < DC; ++d) {
                float4 av = *(const float4*)&As[(d0 + d) * MA + aBase];
                float4 bv = *(const float4*)&B[d * TN + cBase];
                acc[0][0] += fabsf(av.x - bv.x);
                acc[0][1] += fabsf(av.x - bv.y);
                acc[0][2] += fabsf(av.x - bv.z);
                acc[0][3] += fabsf(av.x - bv.w);
                acc[1][0] += fabsf(av.y - bv.x);
                acc[1][1] += fabsf(av.y - bv.y);
                acc[1][2] += fabsf(av.y - bv.z);
                acc[1][3] += fabsf(av.y - bv.w);
                acc[2][0] += fabsf(av.z - bv.x);
                acc[2][1] += fabsf(av.z - bv.y);
                acc[2][2] += fabsf(av.z - bv.z);
                acc[2][3] += fabsf(av.z - bv.w);
                acc[3][0] += fabsf(av.w - bv.x);
                acc[3][1] += fabsf(av.w - bv.y);
                acc[3][2] += fabsf(av.w - bv.z);
                acc[3][3] += fabsf(av.w - bv.w);
            }
            __syncthreads();
        }

        // Write distances into Bs[0]: dist[a][c]
        float* dist = Bs[0];
        #pragma unroll
        for (int i = 0; i < 4; ++i) {
            float4 v = make_float4(acc[i][0], acc[i][1], acc[i][2], acc[i][3]);
            *(float4*)&dist[(aBase + i) * TN + cBase] = v;
        }
        __syncthreads();

        // 16 scanner threads (2 per warp) maintain top-K
        if ((t & 15) == 0) {
            const int a = t >> 4;
            const float* drow = &dist[a * TN];
            float worst = s_kd[a][KNEG - 1];
            for (int c = 0; c < TN; ++c) {
                float dv = drow[c];
                if (dv < worst) {
                    int pos = KNEG - 1;
                    #pragma unroll
                    for (int j = KNEG - 2; j >= 0; --j)
                        if (s_kd[a][j] > dv) pos = j;
                    for (int j = KNEG - 1; j > pos; --j) {
                        s_kd[a][j] = s_kd[a][j - 1];
                        s_ki[a][j] = s_ki[a][j - 1];
                    }
                    s_kd[a][pos] = dv;
                    s_ki[a][pos] = n0 + c;
                    worst = s_kd[a][KNEG - 1];
                }
            }
        }
        __syncthreads();
    }

    if ((t & 15) == 0) {
        int a = t >> 4;
        int tg = tBase + a;
        #pragma unroll
        for (int k = 0; k < KNEG; ++k) {
            g_segkd[dir][tg][seg][k] = s_kd[a][k];
            g_segki[dir][tg][seg][k] = s_ki[a][k];
        }
    }
}

// ---------------- kernel 3: merge segments + loss terms (one warp per t) ----------------
__global__ void loss_kernel(const float* __restrict__ out1, const float* __restrict__ out2,
                            const int* __restrict__ anchor1, const int* __restrict__ anchor2) {
    __shared__ int s_negs[8][KNEG];
    const int warpId = threadIdx.x >> 5;
    const int lane = threadIdx.x & 31;
    const int tt = blockIdx.x * 8 + warpId;

    const float* a1 = out1 + anchor1[tt] * DIM;
    const float* a2 = out2 + anchor2[tt] * DIM;
    float a1v[4], a2v[4];
    #pragma unroll
    for (int j = 0; j < 4; ++j) {
        a1v[j] = a1[lane + 32 * j];
        a2v[j] = a2[lane + 32 * j];
    }
    float A = 0.0f;
    #pragma unroll
    for (int j = 0; j < 4; ++j) A += fabsf(a1v[j] - a2v[j]);
    A = warp_sum(A);
    const float Dm = A + GAMMA;

    float lsum = 0.0f;
    #pragma unroll
    for (int dir = 0; dir < 2; ++dir) {
        if (lane == 0) {
            float kd[KNEG]; int ki[KNEG];
            #pragma unroll
            for (int k = 0; k < KNEG; ++k) { kd[k] = 3.0e38f; ki[k] = 0; }
            for (int s = 0; s < SSEG; ++s) {
                for (int k = 0; k < KNEG; ++k) {
                    float dv = g_segkd[dir][tt][s][k];
                    if (dv < kd[KNEG - 1]) {
                        int pos = KNEG - 1;
                        for (int j = KNEG - 2; j >= 0; --j)
                            if (kd[j] > dv) pos = j;
                        for (int j = KNEG - 1; j > pos; --j) { kd[j] = kd[j - 1]; ki[j] = ki[j - 1]; }
                        kd[pos] = dv; ki[pos] = g_segki[dir][tt][s][k];
                    }
                }
            }
            #pragma unroll
            for (int k = 0; k < KNEG; ++k) s_negs[warpId][k] = ki[k];
        }
        __syncwarp();
        const float* G = (dir == 0) ? out2 : out1;
        #pragma unroll
        for (int k = 0; k < KNEG; ++k) {
            const float* nr = G + s_negs[warpId][k] * DIM;
            float dsum = 0.0f;
            #pragma unroll
            for (int j = 0; j < 4; ++j) {
                float nv = nr[lane + 32 * j];
                float av = (dir == 0) ? a1v[j] : a2v[j];
                dsum += fabsf(av - nv);
            }
            dsum = warp_sum(dsum);
            lsum += fmaxf(Dm - dsum, 0.0f);
        }
        __syncwarp();
    }
    if (lane == 0) g_partial[tt] = lsum;
}

// ---------------- kernel 4: deterministic final reduction ----------------
__global__ void reduce_kernel(float* __restrict__ out) {
    __shared__ float sh[TANCH];
    int t = threadIdx.x;
    sh[t] = g_partial[t];
    __syncthreads();
    #pragma unroll
    for (int s = TANCH / 2; s > 0; s >>= 1) {
        if (t < s) sh[t] += sh[t + s];
        __syncthreads();
    }
    if (t == 0) out[0] = sh[0] * (1.0f / (float)(TANCH * KNEG));
}

// ---------------- launch ----------------
extern "C" void kernel_launch(void* const* d_in, const int* in_sizes, int n_in,
                              void* d_out, int out_size) {
    const float* out1 = (const float*)d_in[0];
    const float* out2 = (const float*)d_in[1];
    const int* anchor1 = (const int*)d_in[2];
    const int* anchor2 = (const int*)d_in[3];
    float* out = (float*)d_out;

    dim3 tb(32, 8);
    dim3 tg(N_PAD / 32, DIM / 32, 2);
    transpose_pad_kernel<<<tg, tb>>>(out1, out2);

    mine_kernel<<<dim3(TANCH / MA, SSEG, 2), 256>>>(out1, out2, anchor1, anchor2);

    loss_kernel<<<TANCH / 8, 256>>>(out1, out2, anchor1, anchor2);

    reduce_kernel<<<1, TANCH>>>(out);
}

// round 2
// speedup vs baseline: 1.6087x; 1.6087x over previous
#include <cuda_runtime.h>
#include <cuda_fp16.h>
#include <cstdint>

#define NPTS 50000
#define DIM  128
#define TANCH 1024
#define KNEG 10
#define MH 16               // per-segment candidate margin
#define GAMMA 1.0f

#define MA 16               // anchors per CTA
#define TN 512              // candidates per tile (fp16)
#define TN2 (TN / 2)        // half2 per row = 256
#define DC 16               // d-chunk
#define NCHUNK (DIM / DC)
#define SSEG 4
#define TILES_PER_SEG 25
#define SEG_LEN (TILES_PER_SEG * TN)   // 12800
#define N_PAD (SSEG * SEG_LEN)         // 51200

// ---------------- static scratch ----------------
__device__ __half g_BTh[2][DIM][N_PAD];          // fp16 transposed, padded with +inf
__device__ float g_segkd[2][TANCH][SSEG][MH];
__device__ int   g_segki[2][TANCH][SSEG][MH];
__device__ float g_partial[2 * TANCH];

// ---------------- helpers ----------------
__device__ __forceinline__ uint32_t h2u(__half2 h) { return *reinterpret_cast<uint32_t*>(&h); }
__device__ __forceinline__ __half2 u2h(uint32_t u) { return *reinterpret_cast<__half2*>(&u); }

__device__ __forceinline__ void cp_async16(uint32_t s, const void* g) {
    asm volatile("cp.async.cg.shared.global [%0], [%1], 16;\n" :: "r"(s), "l"(g));
}
__device__ __forceinline__ void cp_commit() { asm volatile("cp.async.commit_group;\n"); }
template <int N> __device__ __forceinline__ void cp_wait() {
    asm volatile("cp.async.wait_group %0;\n" :: "n"(N));
}
__device__ __forceinline__ float warp_sum(float v) {
    #pragma unroll
    for (int o = 16; o > 0; o >>= 1) v += __shfl_xor_sync(0xffffffffu, v, o);
    return v;
}

// ---------------- kernel 1: transpose + pad + fp16 convert ----------------
__global__ void transpose_pad_kernel(const float* __restrict__ out1,
                                     const float* __restrict__ out2) {
    __shared__ float tile[32][33];
    const float* src = (blockIdx.z == 0) ? out1 : out2;
    __half* dst = &g_BTh[blockIdx.z][0][0];
    int nBase = blockIdx.x * 32;
    int dBase = blockIdx.y * 32;
    #pragma unroll
    for (int j = 0; j < 32; j += 8) {
        int n = nBase + threadIdx.y + j;
        float v = 1.0e30f;   // -> +inf in fp16, never selected
        if (n < NPTS) v = src[n * DIM + dBase + threadIdx.x];
        tile[threadIdx.y + j][threadIdx.x] = v;
    }
    __syncthreads();
    #pragma unroll
    for (int j = 0; j < 32; j += 8) {
        int d = dBase + threadIdx.y + j;
        dst[d * N_PAD + nBase + threadIdx.x] = __float2half(tile[threadIdx.x][threadIdx.y + j]);
    }
}

// ---------------- kernel 2: fp16 mining ----------------
__device__ __forceinline__ void load_chunk_h(uint32_t sbase, const __half* __restrict__ BTh,
                                             int n0, int chunk, int t) {
    #pragma unroll
    for (int i = 0; i < 4; ++i) {
        int f4 = t + i * 256;            // 16B unit within [DC][TN] fp16 tile (1024 units)
        int d  = f4 >> 6;                // 64 units per 512-half row
        int w  = (f4 & 63) * 8;          // half offset within row
        const __half* g = BTh + (chunk * DC + d) * N_PAD + n0 + w;
        cp_async16(sbase + (uint32_t)(f4 * 16), g);
    }
}

__global__ __launch_bounds__(256, 4)
void mine_kernel(const float* __restrict__ out1, const float* __restrict__ out2,
                 const int* __restrict__ anchor1, const int* __restrict__ anchor2) {
    __shared__ uint32_t As2[DIM * MA];      // duplicated half2 anchor values, 8 KB
    __shared__ uint32_t Bs[2][DC * TN2];    // 2 x 16 KB fp16 tiles; Bs[0] reused as dist dump
    __shared__ float s_kd[MA][MH];
    __shared__ int   s_ki[MA][MH];

    const int dir = blockIdx.z;
    const int tBase = blockIdx.x * MA;
    const int seg = blockIdx.y;
    const float* Arows = (dir == 0) ? out1 : out2;
    const int*   anch  = (dir == 0) ? anchor1 : anchor2;
    const __half* BTh  = &g_BTh[(dir == 0) ? 1 : 0][0][0];

    const int t = threadIdx.x;

    // Load 16 anchor rows, convert to duplicated half2, transposed As2[d][a]
    {
        int a  = t >> 4;
        int d0 = (t & 15) * 8;
        const float* row = Arows + anch[tBase + a] * DIM;
        #pragma unroll
        for (int j = 0; j < 8; ++j) {
            __half hv = __float2half(row[d0 + j]);
            As2[(d0 + j) * MA + a] = h2u(__half2half2(hv));
        }
    }
    if (t < MA) {
        #pragma unroll
        for (int k = 0; k < MH; ++k) { s_kd[t][k] = 3.0e38f; s_ki[t][k] = 0; }
    }
    __syncthreads();

    const int aB = (t >> 6) * 4;     // warp-uniform anchor base
    const int cB = (t & 63) * 4;     // half2 unit base (8 candidates per thread)
    const int segStart = seg * SEG_LEN;
    const uint32_t sb0 = (uint32_t)__cvta_generic_to_shared(Bs[0]);
    const uint32_t sb1 = (uint32_t)__cvta_generic_to_shared(Bs[1]);

    for (int tile = 0; tile < TILES_PER_SEG; ++tile) {
        const int n0 = segStart + tile * TN;
        __half2 acc[4][4];
        #pragma unroll
        for (int i = 0; i < 4; ++i)
            #pragma unroll
            for (int j = 0; j < 4; ++j) acc[i][j] = __float2half2_rn(0.0f);

        load_chunk_h(sb0, BTh, n0, 0, t);
        cp_commit();

        for (int c = 0; c < NCHUNK; ++c) {
            if (c + 1 < NCHUNK) {
                load_chunk_h((c & 1) ? sb0 : sb1, BTh, n0, c + 1, t);
                cp_commit();
                cp_wait<1>();
            } else {
                cp_wait<0>();
            }
            __syncthreads();
            const uint32_t* B = Bs[c & 1];
            const int d0g = c * DC;
            #pragma unroll
            for (int d = 0; d < DC; ++d) {
                uint4 au = *(const uint4*)&As2[(d0g + d) * MA + aB];
                uint4 bu = *(const uint4*)&B[d * TN2 + cB];
                __half2 a0 = u2h(au.x), a1 = u2h(au.y), a2 = u2h(au.z), a3 = u2h(au.w);
                __half2 b0 = u2h(bu.x), b1 = u2h(bu.y), b2 = u2h(bu.z), b3 = u2h(bu.w);
                acc[0][0] = __hadd2(acc[0][0], __habs2(__hsub2(a0, b0)));
                acc[0][1] = __hadd2(acc[0][1], __habs2(__hsub2(a0, b1)));
                acc[0][2] = __hadd2(acc[0][2], __habs2(__hsub2(a0, b2)));
                acc[0][3] = __hadd2(acc[0][3], __habs2(__hsub2(a0, b3)));
                acc[1][0] = __hadd2(acc[1][0], __habs2(__hsub2(a1, b0)));
                acc[1][1] = __hadd2(acc[1][1], __habs2(__hsub2(a1, b1)));
                acc[1][2] = __hadd2(acc[1][2], __habs2(__hsub2(a1, b2)));
                acc[1][3] = __hadd2(acc[1][3], __habs2(__hsub2(a1, b3)));
                acc[2][0] = __hadd2(acc[2][0], __habs2(__hsub2(a2, b0)));
                acc[2][1] = __hadd2(acc[2][1], __habs2(__hsub2(a2, b1)));
                acc[2][2] = __hadd2(acc[2][2], __habs2(__hsub2(a2, b2)));
                acc[2][3] = __hadd2(acc[2][3], __habs2(__hsub2(a2, b3)));
                acc[3][0] = __hadd2(acc[3][0], __habs2(__hsub2(a3, b0)));
                acc[3][1] = __hadd2(acc[3][1], __habs2(__hsub2(a3, b1)));
                acc[3][2] = __hadd2(acc[3][2], __habs2(__hsub2(a3, b2)));
                acc[3][3] = __hadd2(acc[3][3], __habs2(__hsub2(a3, b3)));
            }
            __syncthreads();
        }

        // Dump fp16 distance pairs into Bs[0]: dist[a][c2]
        uint32_t* dist = Bs[0];
        #pragma unroll
        for (int i = 0; i < 4; ++i) {
            uint4 w;
            w.x = h2u(acc[i][0]); w.y = h2u(acc[i][1]);
            w.z = h2u(acc[i][2]); w.w = h2u(acc[i][3]);
            *(uint4*)&dist[(aB + i) * TN2 + cB] = w;
        }
        __syncthreads();

        // 16 scanner threads: vectorized early-out scan, rare insertion
        if ((t & 15) == 0) {
            const int a = t >> 4;
            const uint32_t* drow = &dist[a * TN2];
            float worst = s_kd[a][MH - 1];
            for (int u = 0; u < TN2 / 4; ++u) {     // 64 iters, 8 candidates each
                uint4 v = *(const uint4*)&drow[u * 4];
                __half2 m = __hmin2(__hmin2(u2h(v.x), u2h(v.y)),
                                    __hmin2(u2h(v.z), u2h(v.w)));
                float mn = __half2float(__hmin(__low2half(m), __high2half(m)));
                if (mn < worst) {
                    uint32_t uu[4] = {v.x, v.y, v.z, v.w};
                    #pragma unroll
                    for (int j = 0; j < 4; ++j) {
                        __half2 p = u2h(uu[j]);
                        #pragma unroll
                        for (int l = 0; l < 2; ++l) {
                            float dv = __half2float(l ? __high2half(p) : __low2half(p));
                            if (dv < worst) {
                                int ct = u * 8 + j * 2 + l;
                                int pos = MH - 1;
                                for (int q = MH - 2; q >= 0; --q)
                                    if (s_kd[a][q] > dv) pos = q;
                                for (int q = MH - 1; q > pos; --q) {
                                    s_kd[a][q] = s_kd[a][q - 1];
                                    s_ki[a][q] = s_ki[a][q - 1];
                                }
                                s_kd[a][pos] = dv;
                                s_ki[a][pos] = n0 + ct;
                                worst = s_kd[a][MH - 1];
                            }
                        }
                    }
                }
            }
        }
        __syncthreads();
    }

    if ((t & 15) == 0) {
        int a = t >> 4;
        int tg = tBase + a;
        #pragma unroll
        for (int k = 0; k < MH; ++k) {
            g_segkd[dir][tg][seg][k] = s_kd[a][k];
            g_segki[dir][tg][seg][k] = s_ki[a][k];
        }
    }
}

// ---------------- kernel 3: exact fp32 re-rank over 64 candidates + loss ----------------
__global__ void refine_loss_kernel(const float* __restrict__ out1, const float* __restrict__ out2,
                                   const int* __restrict__ anchor1, const int* __restrict__ anchor2) {
    const int g = blockIdx.x * 8 + (threadIdx.x >> 5);
    const int lane = threadIdx.x & 31;
    const int dir = g >> 10;
    const int tt = g & 1023;

    const float* r1 = out1 + anchor1[tt] * DIM;
    const float* r2 = out2 + anchor2[tt] * DIM;
    float v1[4], v2[4];
    #pragma unroll
    for (int j = 0; j < 4; ++j) {
        v1[j] = r1[lane + 32 * j];
        v2[j] = r2[lane + 32 * j];
    }
    float A = 0.0f;
    #pragma unroll
    for (int j = 0; j < 4; ++j) A += fabsf(v1[j] - v2[j]);
    A = warp_sum(A);
    const float Dm = A + GAMMA;

    float selfv[4];
    #pragma unroll
    for (int j = 0; j < 4; ++j) selfv[j] = (dir == 0) ? v1[j] : v2[j];
    const float* G = (dir == 0) ? out2 : out1;

    float kd[KNEG]; int ki[KNEG];
    #pragma unroll
    for (int k = 0; k < KNEG; ++k) { kd[k] = 3.0e38f; ki[k] = 0x7fffffff; }

    for (int k = 0; k < SSEG * MH; ++k) {
        const int idx = g_segki[dir][tt][k >> 4][k & 15];
        const float* nr = G + idx * DIM;
        float dsum = 0.0f;
        #pragma unroll
        for (int j = 0; j < 4; ++j) dsum += fabsf(selfv[j] - nr[lane + 32 * j]);
        dsum = warp_sum(dsum);
        if (lane == 0) {
            bool better = (dsum < kd[KNEG - 1]) ||
                          (dsum == kd[KNEG - 1] && idx < ki[KNEG - 1]);
            if (better) {
                int pos = KNEG - 1;
                for (int q = KNEG - 2; q >= 0; --q)
                    if (kd[q] > dsum || (kd[q] == dsum && ki[q] > idx)) pos = q;
                for (int q = KNEG - 1; q > pos; --q) { kd[q] = kd[q - 1]; ki[q] = ki[q - 1]; }
                kd[pos] = dsum; ki[pos] = idx;
            }
        }
    }
    if (lane == 0) {
        float lsum = 0.0f;
        #pragma unroll
        for (int k = 0; k < KNEG; ++k) lsum += fmaxf(Dm - kd[k], 0.0f);
        g_partial[g] = lsum;
    }
}

// ---------------- kernel 4: deterministic reduction ----------------
__global__ void reduce_kernel(float* __restrict__ out) {
    __shared__ float sh[1024];
    int t = threadIdx.x;
    sh[t] = g_partial[t] + g_partial[t + 1024];
    __syncthreads();
    #pragma unroll
    for (int s = 512; s > 0; s >>= 1) {
        if (t < s) sh[t] += sh[t + s];
        __syncthreads();
    }
    if (t == 0) out[0] = sh[0] * (1.0f / (float)(TANCH * KNEG));
}

// ---------------- launch ----------------
extern "C" void kernel_launch(void* const* d_in, const int* in_sizes, int n_in,
                              void* d_out, int out_size) {
    const float* out1 = (const float*)d_in[0];
    const float* out2 = (const float*)d_in[1];
    const int* anchor1 = (const int*)d_in[2];
    const int* anchor2 = (const int*)d_in[3];
    float* out = (float*)d_out;

    dim3 tb(32, 8);
    dim3 tg(N_PAD / 32, DIM / 32, 2);
    transpose_pad_kernel<<<tg, tb>>>(out1, out2);

    mine_kernel<<<dim3(TANCH / MA, SSEG, 2), 256>>>(out1, out2, anchor1, anchor2);

    refine_loss_kernel<<<2 * TANCH / 8, 256>>>(out1, out2, anchor1, anchor2);

    reduce_kernel<<<1, 1024>>>(out);
}

// round 3
// speedup vs baseline: 2.5008x; 1.5545x over previous
#include <cuda_runtime.h>
#include <cstdint>

#define NPTS 50000
#define DIM  128
#define W4   (DIM / 4)       // 32 packed words per point
#define TANCH 1024
#define KNEG 10
#define MH 16                // per-segment candidate margin
#define GAMMA 1.0f
#define QSCALE 20.0f

#define MA 16                // anchors per CTA
#define TN 256               // candidates per tile
#define CW 8                 // words per chunk (32 dims)
#define NCH (W4 / CW)        // 4 chunks per tile
#define STAGES 3
#define SSEG 4
#define TILES_PER_SEG 50
#define SEG_LEN (TILES_PER_SEG * TN)    // 12800
#define N_PAD (SSEG * SEG_LEN)          // 51200
#define TOTCH (TILES_PER_SEG * NCH)     // 200 chunks per CTA stream

// ---------------- static scratch ----------------
__device__ uint32_t g_BTq[2][W4][N_PAD];   // packed u8x4, transposed, pad=0xFF
__device__ int   g_segki[2][TANCH][SSEG][MH];
__device__ float g_partial[2 * TANCH];

// ---------------- helpers ----------------
__device__ __forceinline__ int sad4(int acc, uint32_t a, uint32_t b) {
    int r;
    asm("vabsdiff4.u32.u32.u32.add %0, %1, %2, %3;" : "=r"(r) : "r"(a), "r"(b), "r"(acc));
    return r;
}
__device__ __forceinline__ uint32_t quant4(float4 v) {
    int q0 = min(127, max(-127, __float2int_rn(v.x * QSCALE))) + 128;
    int q1 = min(127, max(-127, __float2int_rn(v.y * QSCALE))) + 128;
    int q2 = min(127, max(-127, __float2int_rn(v.z * QSCALE))) + 128;
    int q3 = min(127, max(-127, __float2int_rn(v.w * QSCALE))) + 128;
    return (uint32_t)q0 | ((uint32_t)q1 << 8) | ((uint32_t)q2 << 16) | ((uint32_t)q3 << 24);
}
__device__ __forceinline__ void cp_async16(uint32_t s, const void* g) {
    asm volatile("cp.async.cg.shared.global [%0], [%1], 16;\n" :: "r"(s), "l"(g));
}
__device__ __forceinline__ void cp_commit() { asm volatile("cp.async.commit_group;\n"); }
template <int N> __device__ __forceinline__ void cp_wait() {
    asm volatile("cp.async.wait_group %0;\n" :: "n"(N));
}
__device__ __forceinline__ float warp_sum(float v) {
    #pragma unroll
    for (int o = 16; o > 0; o >>= 1) v += __shfl_xor_sync(0xffffffffu, v, o);
    return v;
}

// ---------------- kernel 1: quantize + pack + transpose ----------------
__global__ void quant_transpose_kernel(const float* __restrict__ out1,
                                       const float* __restrict__ out2) {
    __shared__ uint32_t tile[32][33];
    const float* src = (blockIdx.z == 0) ? out1 : out2;
    uint32_t* dst = &g_BTq[blockIdx.z][0][0];
    const int nBase = blockIdx.x * 32;
    const int tx = threadIdx.x, ty = threadIdx.y;
    #pragma unroll
    for (int j = 0; j < 32; j += 8) {
        int n = nBase + ty + j;
        uint32_t w = 0xFFFFFFFFu;
        if (n < NPTS) w = quant4(*(const float4*)(src + n * DIM + 4 * tx));
        tile[ty + j][tx] = w;
    }
    __syncthreads();
    #pragma unroll
    for (int j = 0; j < 32; j += 8) {
        int d4 = ty + j;
        dst[d4 * N_PAD + nBase + tx] = tile[tx][d4];
    }
}

// ---------------- kernel 2: int8 SAD mining ----------------
__global__ __launch_bounds__(256, 4)
void mine_kernel(const float* __restrict__ out1, const float* __restrict__ out2,
                 const int* __restrict__ anchor1, const int* __restrict__ anchor2) {
    __shared__ uint32_t Aq[W4][MA];                // 2 KB
    __shared__ uint32_t Bq[STAGES][CW][TN];        // 24 KB
    __shared__ int s_kd[MA][MH];
    __shared__ int s_ki[MA][MH];

    const int dir = blockIdx.z;
    const int tBase = blockIdx.x * MA;
    const int seg = blockIdx.y;
    const float* Arows = (dir == 0) ? out1 : out2;
    const int*   anch  = (dir == 0) ? anchor1 : anchor2;
    const uint32_t* BTq = &g_BTq[(dir == 0) ? 1 : 0][0][0];

    const int t = threadIdx.x;
    const int lane = t & 31;
    const int aB = (t >> 5) * 2;          // warp-uniform: this warp owns anchors aB, aB+1
    const int cB = lane * 8;              // 8 candidates per thread
    const int segStart = seg * SEG_LEN;

    // quantize 16 anchor rows into Aq[word][anchor]
    #pragma unroll
    for (int i = 0; i < 2; ++i) {
        int id = t + 256 * i;
        int a = id >> 5, w = id & 31;
        float4 v = *(const float4*)(Arows + anch[tBase + a] * DIM + 4 * w);
        Aq[w][a] = quant4(v);
    }
    if (t < MA) {
        #pragma unroll
        for (int k = 0; k < MH; ++k) { s_kd[t][k] = 0x7fffffff; s_ki[t][k] = 0; }
    }
    __syncthreads();

    // chunk loader
    auto load_chunk = [&](int s, int g) {
        uint32_t sb = (uint32_t)__cvta_generic_to_shared(&Bq[s][0][0]);
        const int n0 = segStart + (g >> 2) * TN;
        const int rowBase = (g & 3) * CW;
        #pragma unroll
        for (int i = 0; i < 2; ++i) {
            int id = t + 256 * i;               // 512 x 16B units
            int r = id >> 6;
            int c4 = (id & 63) * 4;
            const uint32_t* gp = BTq + (rowBase + r) * N_PAD + n0 + c4;
            cp_async16(sb + (uint32_t)((r * TN + c4) * 4), gp);
        }
        cp_commit();
    };

    load_chunk(0, 0);
    load_chunk(1, 1);

    int worst0 = 0x7fffffff, worst1 = 0x7fffffff;   // valid in lane 0

    for (int tile = 0; tile < TILES_PER_SEG; ++tile) {
        int acc0[8], acc1[8];
        #pragma unroll
        for (int j = 0; j < 8; ++j) { acc0[j] = 0; acc1[j] = 0; }

        #pragma unroll
        for (int c = 0; c < NCH; ++c) {
            const int g = tile * NCH + c;
            if (g + 1 < TOTCH) cp_wait<1>(); else cp_wait<0>();
            __syncthreads();
            if (g + 2 < TOTCH) load_chunk((g + 2) % STAGES, g + 2);

            const uint32_t* B = &Bq[g % STAGES][0][0];
            const int wg = c * CW;
            #pragma unroll
            for (int w = 0; w < CW; ++w) {
                uint2 aw = *(const uint2*)&Aq[wg + w][aB];
                uint4 b0 = *(const uint4*)&B[w * TN + cB];
                uint4 b1 = *(const uint4*)&B[w * TN + cB + 4];
                acc0[0] = sad4(acc0[0], aw.x, b0.x);
                acc0[1] = sad4(acc0[1], aw.x, b0.y);
                acc0[2] = sad4(acc0[2], aw.x, b0.z);
                acc0[3] = sad4(acc0[3], aw.x, b0.w);
                acc0[4] = sad4(acc0[4], aw.x, b1.x);
                acc0[5] = sad4(acc0[5], aw.x, b1.y);
                acc0[6] = sad4(acc0[6], aw.x, b1.z);
                acc0[7] = sad4(acc0[7], aw.x, b1.w);
                acc1[0] = sad4(acc1[0], aw.y, b0.x);
                acc1[1] = sad4(acc1[1], aw.y, b0.y);
                acc1[2] = sad4(acc1[2], aw.y, b0.z);
                acc1[3] = sad4(acc1[3], aw.y, b0.w);
                acc1[4] = sad4(acc1[4], aw.y, b1.x);
                acc1[5] = sad4(acc1[5], aw.y, b1.y);
                acc1[6] = sad4(acc1[6], aw.y, b1.z);
                acc1[7] = sad4(acc1[7], aw.y, b1.w);
            }
        }

        // ballot filter: rare survivors inserted serially by lane 0
        const int n0 = segStart + tile * TN;
        int w0v = __shfl_sync(0xffffffffu, worst0, 0);
        int w1v = __shfl_sync(0xffffffffu, worst1, 0);
        #pragma unroll
        for (int j = 0; j < 8; ++j) {
            unsigned m0 = __ballot_sync(0xffffffffu, acc0[j] < w0v);
            while (m0) {
                int src = __ffs(m0) - 1; m0 &= m0 - 1;
                int d = __shfl_sync(0xffffffffu, acc0[j], src);
                if (lane == 0 && d < worst0) {
                    int idx = n0 + src * 8 + j;
                    int pos = MH - 1;
                    #pragma unroll
                    for (int q = MH - 2; q >= 0; --q)
                        if (s_kd[aB][q] > d) pos = q;
                    for (int q = MH - 1; q > pos; --q) {
                        s_kd[aB][q] = s_kd[aB][q - 1];
                        s_ki[aB][q] = s_ki[aB][q - 1];
                    }
                    s_kd[aB][pos] = d; s_ki[aB][pos] = idx;
                    worst0 = s_kd[aB][MH - 1];
                }
            }
            unsigned m1 = __ballot_sync(0xffffffffu, acc1[j] < w1v);
            while (m1) {
                int src = __ffs(m1) - 1; m1 &= m1 - 1;
                int d = __shfl_sync(0xffffffffu, acc1[j], src);
                if (lane == 0 && d < worst1) {
                    int idx = n0 + src * 8 + j;
                    int pos = MH - 1;
                    #pragma unroll
                    for (int q = MH - 2; q >= 0; --q)
                        if (s_kd[aB + 1][q] > d) pos = q;
                    for (int q = MH - 1; q > pos; --q) {
                        s_kd[aB + 1][q] = s_kd[aB + 1][q - 1];
                        s_ki[aB + 1][q] = s_ki[aB + 1][q - 1];
                    }
                    s_kd[aB + 1][pos] = d; s_ki[aB + 1][pos] = idx;
                    worst1 = s_kd[aB + 1][MH - 1];
                }
            }
        }
    }

    if (lane == 0) {
        #pragma unroll
        for (int k = 0; k < MH; ++k) {
            g_segki[dir][tBase + aB][seg][k]     = s_ki[aB][k];
            g_segki[dir][tBase + aB + 1][seg][k] = s_ki[aB + 1][k];
        }
    }
}

// ---------------- kernel 3: exact fp32 re-rank over 64 candidates + loss ----------------
__global__ void refine_loss_kernel(const float* __restrict__ out1, const float* __restrict__ out2,
                                   const int* __restrict__ anchor1, const int* __restrict__ anchor2) {
    const int g = blockIdx.x * 8 + (threadIdx.x >> 5);
    const int lane = threadIdx.x & 31;
    const int dir = g >> 10;
    const int tt = g & 1023;

    const float* r1 = out1 + anchor1[tt] * DIM;
    const float* r2 = out2 + anchor2[tt] * DIM;
    float v1[4], v2[4];
    #pragma unroll
    for (int j = 0; j < 4; ++j) {
        v1[j] = r1[lane + 32 * j];
        v2[j] = r2[lane + 32 * j];
    }
    float A = 0.0f;
    #pragma unroll
    for (int j = 0; j < 4; ++j) A += fabsf(v1[j] - v2[j]);
    A = warp_sum(A);
    const float Dm = A + GAMMA;

    float selfv[4];
    #pragma unroll
    for (int j = 0; j < 4; ++j) selfv[j] = (dir == 0) ? v1[j] : v2[j];
    const float* G = (dir == 0) ? out2 : out1;

    float kd[KNEG]; int ki[KNEG];
    #pragma unroll
    for (int k = 0; k < KNEG; ++k) { kd[k] = 3.0e38f; ki[k] = 0x7fffffff; }

    for (int k = 0; k < SSEG * MH; ++k) {
        int idx = g_segki[dir][tt][k >> 4][k & (MH - 1)];
        idx = min(idx, NPTS - 1);
        const float* nr = G + idx * DIM;
        float dsum = 0.0f;
        #pragma unroll
        for (int j = 0; j < 4; ++j) dsum += fabsf(selfv[j] - nr[lane + 32 * j]);
        dsum = warp_sum(dsum);
        if (lane == 0) {
            bool better = (dsum < kd[KNEG - 1]) ||
                          (dsum == kd[KNEG - 1] && idx < ki[KNEG - 1]);
            if (better) {
                int pos = KNEG - 1;
                for (int q = KNEG - 2; q >= 0; --q)
                    if (kd[q] > dsum || (kd[q] == dsum && ki[q] > idx)) pos = q;
                for (int q = KNEG - 1; q > pos; --q) { kd[q] = kd[q - 1]; ki[q] = ki[q - 1]; }
                kd[pos] = dsum; ki[pos] = idx;
            }
        }
    }
    if (lane == 0) {
        float lsum = 0.0f;
        #pragma unroll
        for (int k = 0; k < KNEG; ++k) lsum += fmaxf(Dm - kd[k], 0.0f);
        g_partial[g] = lsum;
    }
}

// ---------------- kernel 4: deterministic reduction ----------------
__global__ void reduce_kernel(float* __restrict__ out) {
    __shared__ float sh[1024];
    int t = threadIdx.x;
    sh[t] = g_partial[t] + g_partial[t + 1024];
    __syncthreads();
    #pragma unroll
    for (int s = 512; s > 0; s >>= 1) {
        if (t < s) sh[t] += sh[t + s];
        __syncthreads();
    }
    if (t == 0) out[0] = sh[0] * (1.0f / (float)(TANCH * KNEG));
}

// ---------------- launch ----------------
extern "C" void kernel_launch(void* const* d_in, const int* in_sizes, int n_in,
                              void* d_out, int out_size) {
    const float* out1 = (const float*)d_in[0];
    const float* out2 = (const float*)d_in[1];
    const int* anchor1 = (const int*)d_in[2];
    const int* anchor2 = (const int*)d_in[3];
    float* out = (float*)d_out;

    quant_transpose_kernel<<<dim3(N_PAD / 32, 1, 2), dim3(32, 8)>>>(out1, out2);

    mine_kernel<<<dim3(TANCH / MA, SSEG, 2), 256>>>(out1, out2, anchor1, anchor2);

    refine_loss_kernel<<<2 * TANCH / 8, 256>>>(out1, out2, anchor1, anchor2);

    reduce_kernel<<<1, 1024>>>(out);
}